// round 1
// baseline (speedup 1.0000x reference)
#include <cuda_runtime.h>
#include <math.h>

// Problem constants
#define B_   4096
#define N_   8192          // 2B rows
#define C_   128           // feature dim
#define RI   64            // rows per block
#define RJ   64            // cols per tile
#define NTILES (N_ / RJ)   // 128
#define NBLK   (N_ / RI)   // 128

// Scratch (allocation-free: __device__ globals)
__device__ float g_RN_T[C_ * N_];     // normalized reps, TRANSPOSED: [k][row]
__device__ float g_partial[NBLK];     // per-block loss partial sums

// ---------------------------------------------------------------------------
// Kernel 1: L2-normalize each row of [z_i; z_j], store transposed (k-major).
// One block = 32 rows, 256 threads (8 warps, 1 row per warp per pass).
// ---------------------------------------------------------------------------
__global__ void __launch_bounds__(256) normalize_kernel(
    const float* __restrict__ zi, const float* __restrict__ zj)
{
    __shared__ float s[32][C_ + 1];   // +1 pad: conflict-free transposed read
    __shared__ float snorm[32];

    const int rbase = blockIdx.x * 32;
    const int warp  = threadIdx.x >> 5;
    const int lane  = threadIdx.x & 31;

    #pragma unroll
    for (int rr = warp; rr < 32; rr += 8) {
        const int r = rbase + rr;
        const float* src = (r < B_) ? (zi + (size_t)r * C_)
                                    : (zj + (size_t)(r - B_) * C_);
        float4 v = ((const float4*)src)[lane];
        s[rr][lane * 4 + 0] = v.x;
        s[rr][lane * 4 + 1] = v.y;
        s[rr][lane * 4 + 2] = v.z;
        s[rr][lane * 4 + 3] = v.w;
        float ss = v.x * v.x + v.y * v.y + v.z * v.z + v.w * v.w;
        #pragma unroll
        for (int o = 16; o; o >>= 1) ss += __shfl_xor_sync(0xffffffffu, ss, o);
        if (lane == 0) snorm[rr] = rsqrtf(ss);
    }
    __syncthreads();

    // Write transposed: consecutive lanes -> consecutive rows (coalesced GMEM,
    // conflict-free smem via the +1 pad).
    #pragma unroll
    for (int m = 0; m < 16; m++) {
        int idx = m * 256 + threadIdx.x;   // 0..4095
        int k = idx >> 5;                  // 0..127
        int r = idx & 31;                  // 0..31
        g_RN_T[k * N_ + rbase + r] = s[r][k] * snorm[r];
    }
}

// ---------------------------------------------------------------------------
// Kernel 2: fused sim-GEMM + softmax-denominator reduction.
// Block = 64 rows (ibase), loops over 128 column tiles of 64.
// 256 threads, each owns a 4x4 micro-tile: ti = t&15 (row group),
// tj = t>>4 (col group). Both smem tiles are k-major (loaded straight from
// the transposed global layout -> conflict-free stores AND loads).
// ---------------------------------------------------------------------------
extern __shared__ float smem_dyn[];

__global__ void __launch_bounds__(256) ntxent_main_kernel()
{
    float* sA   = smem_dyn;               // [C_][RI]  32KB
    float* sB   = sA + C_ * RI;           // [C_][RJ]  32KB
    float* sSum = sB + C_ * RJ;           // [16][RI]   4KB
    float* sPos = sSum + 16 * RI;         // [RI]      256B

    const int t  = threadIdx.x;
    const int ti = t & 15;
    const int tj = t >> 4;
    const int ibase = blockIdx.x * RI;

    // Load this block's 64 rows (k-major) once.
    #pragma unroll
    for (int m = 0; m < 8; m++) {
        int idx = m * 256 + t;
        int k = idx >> 4, q = idx & 15;
        *(float4*)&sA[k * RI + q * 4] =
            *(const float4*)&g_RN_T[k * N_ + ibase + q * 4];
    }

    float rowsum[4] = {0.f, 0.f, 0.f, 0.f};
    const int i0   = ibase + ti * 4;
    const int pos0 = (i0 + B_) & (N_ - 1);   // pos col for row i0+u is pos0+u
                                             // (no wrap inside the group of 4)

    for (int tile = 0; tile < NTILES; tile++) {
        const int jbase = tile * RJ;
        __syncthreads();   // previous compute done (also publishes sA on tile 0)
        #pragma unroll
        for (int m = 0; m < 8; m++) {
            int idx = m * 256 + t;
            int k = idx >> 4, q = idx & 15;
            *(float4*)&sB[k * RJ + q * 4] =
                *(const float4*)&g_RN_T[k * N_ + jbase + q * 4];
        }
        __syncthreads();

        float acc[4][4];
        #pragma unroll
        for (int u = 0; u < 4; u++)
            #pragma unroll
            for (int v = 0; v < 4; v++) acc[u][v] = 0.f;

        #pragma unroll 8
        for (int k = 0; k < C_; k++) {
            float4 a = *(const float4*)&sA[k * RI + ti * 4];
            float4 b = *(const float4*)&sB[k * RJ + tj * 4];
            const float av[4] = {a.x, a.y, a.z, a.w};
            const float bv[4] = {b.x, b.y, b.z, b.w};
            #pragma unroll
            for (int u = 0; u < 4; u++)
                #pragma unroll
                for (int v = 0; v < 4; v++)
                    acc[u][v] = fmaf(av[u], bv[v], acc[u][v]);
        }

        // Fused epilogue: exp(sim/T), mask diag, capture positive pair.
        const int j0 = jbase + tj * 4;
        #pragma unroll
        for (int u = 0; u < 4; u++) {
            const int i    = i0 + u;
            const int posj = pos0 + u;
            #pragma unroll
            for (int v = 0; v < 4; v++) {
                const int j = j0 + v;
                const float d = acc[u][v];
                float e = __expf(2.0f * d);          // sim / T, T = 0.5
                if (j == i)    e = 0.f;              // diag masked to -inf
                if (j == posj) sPos[ti * 4 + u] = d; // unique writer per row
                rowsum[u] += e;
            }
        }
    }

    // Cross-thread row reduction (16 tj-partials per row).
    #pragma unroll
    for (int u = 0; u < 4; u++)
        sSum[tj * RI + ti * 4 + u] = rowsum[u];
    __syncthreads();

    if (t < RI) {
        float tot = 0.f;
        #pragma unroll
        for (int w = 0; w < 16; w++) tot += sSum[w * RI + t];
        const float p2 = 2.0f * sPos[t];             // pos / T
        // loss_i = LSE(logits_i) - pos/T ; denom adds the prepended pos col.
        float c = logf(tot + __expf(p2)) - p2;
        #pragma unroll
        for (int o = 16; o; o >>= 1) c += __shfl_xor_sync(0xffffffffu, c, o);
        if ((t & 31) == 0) sPos[t >> 5] = c;         // reuse (disjoint addrs)
    }
    __syncthreads();
    if (t == 0) g_partial[blockIdx.x] = sPos[0] + sPos[1];
}

// ---------------------------------------------------------------------------
// Kernel 3: reduce 128 block partials, divide by 2B, write scalar loss.
// ---------------------------------------------------------------------------
__global__ void __launch_bounds__(128) finalize_kernel(float* __restrict__ out)
{
    const int t = threadIdx.x;            // 128 threads
    float v = g_partial[t];
    #pragma unroll
    for (int o = 16; o; o >>= 1) v += __shfl_xor_sync(0xffffffffu, v, o);
    __shared__ float sw[4];
    if ((t & 31) == 0) sw[t >> 5] = v;
    __syncthreads();
    if (t == 0) out[0] = (sw[0] + sw[1] + sw[2] + sw[3]) * (1.0f / (float)N_);
}

// ---------------------------------------------------------------------------
extern "C" void kernel_launch(void* const* d_in, const int* in_sizes, int n_in,
                              void* d_out, int out_size)
{
    const float* zi = (const float*)d_in[0];
    const float* zj = (const float*)d_in[1];
    float* out = (float*)d_out;

    const size_t smem_bytes = (size_t)(C_ * RI + C_ * RJ + 16 * RI + RI) * sizeof(float);
    cudaFuncSetAttribute(ntxent_main_kernel,
                         cudaFuncAttributeMaxDynamicSharedMemorySize,
                         (int)smem_bytes);

    normalize_kernel<<<N_ / 32, 256>>>(zi, zj);
    ntxent_main_kernel<<<NBLK, 256, smem_bytes>>>();
    finalize_kernel<<<1, 128>>>(out);
}

// round 8
// speedup vs baseline: 9.5179x; 9.5179x over previous
#include <cuda_runtime.h>
#include <cuda_bf16.h>
#include <math.h>
#include <stdint.h>

// ---------------------------------------------------------------- constants
#define B_      4096
#define N_      8192              // 2B rows
#define C_      128               // feature dim
#define MT      128               // rows per CTA stripe
#define NT      128               // cols per j-tile
#define TT      32                // tiles per j-half (4096/128)
#define THREADS 256
#define PITCH   272               // smem row pitch (256B data + 16B pad)
#define LOG2E2  2.8853900817779268f   // 2 / T * log2(e), T = 0.5 -> 2*log2(e)

// scratch (__device__ globals: allocation-free)
__device__ __nv_bfloat16 g_RB[N_ * C_];   // normalized reps, bf16, row-major
__device__ float g_rowsum[N_];            // sum_j exp(2*sim_ij), diag excluded
__device__ float g_pos[N_];               // sim(i, (i+B) mod N)

// ---------------------------------------------------------------- helpers
__device__ __forceinline__ uint32_t smem_u32(const void* p) {
    uint32_t a;
    asm("{ .reg .u64 t; cvta.to.shared.u64 t, %1; cvt.u32.u64 %0, t; }"
        : "=r"(a) : "l"(p));
    return a;
}

__device__ __forceinline__ void ldsm_x4(uint32_t (&r)[4], uint32_t addr) {
    asm volatile("ldmatrix.sync.aligned.m8n8.x4.shared.b16 {%0,%1,%2,%3}, [%4];"
                 : "=r"(r[0]), "=r"(r[1]), "=r"(r[2]), "=r"(r[3]) : "r"(addr));
}

__device__ __forceinline__ void mma16816(float (&d)[4], const uint32_t (&a)[4],
                                         uint32_t b0, uint32_t b1) {
    asm volatile(
        "mma.sync.aligned.m16n8k16.row.col.f32.bf16.bf16.f32 "
        "{%0,%1,%2,%3}, {%4,%5,%6,%7}, {%8,%9}, {%0,%1,%2,%3};"
        : "+f"(d[0]), "+f"(d[1]), "+f"(d[2]), "+f"(d[3])
        : "r"(a[0]), "r"(a[1]), "r"(a[2]), "r"(a[3]), "r"(b0), "r"(b1));
}

__device__ __forceinline__ float ex2(float x) {
    float r;
    asm("ex2.approx.f32 %0, %1;" : "=f"(r) : "f"(x));
    return r;
}

// ---------------------------------------------------------------- kernel 1
// L2-normalize rows of [z_i; z_j] -> bf16 row-major. One warp per row.
// Also zero g_rowsum.
__global__ void __launch_bounds__(256) normalize_kernel(
    const float* __restrict__ zi, const float* __restrict__ zj)
{
    const int w = threadIdx.x >> 5, lane = threadIdx.x & 31;
    const int row = blockIdx.x * 8 + w;
    const float* src = (row < B_) ? (zi + (size_t)row * C_)
                                  : (zj + (size_t)(row - B_) * C_);
    float4 v = ((const float4*)src)[lane];
    float ss = v.x * v.x + v.y * v.y + v.z * v.z + v.w * v.w;
    #pragma unroll
    for (int o = 16; o; o >>= 1) ss += __shfl_xor_sync(0xffffffffu, ss, o);
    const float rn = rsqrtf(ss);
    __nv_bfloat162 h0 = __floats2bfloat162_rn(v.x * rn, v.y * rn);
    __nv_bfloat162 h1 = __floats2bfloat162_rn(v.z * rn, v.w * rn);
    uint2 p;
    p.x = *(uint32_t*)&h0;
    p.y = *(uint32_t*)&h1;
    ((uint2*)(g_RB + (size_t)row * C_))[lane] = p;

    if (blockIdx.x < 32) g_rowsum[blockIdx.x * 256 + threadIdx.x] = 0.f;
}

// ---------------------------------------------------------------- kernel 2
// Fused sim-GEMM (mma.sync bf16 HMMA) + exp-rowsum epilogue in registers.
// CTA = (i-stripe of 128 rows) x (j-half of 4096 cols), 32 tiles of 128.
// 8 warps in 4(m) x 2(n): warp tile 32x64. Double-buffered B in smem.
extern "C" __global__ void __launch_bounds__(THREADS, 1) ntxent_mma_kernel()
{
    extern __shared__ char smraw[];
    const uint32_t sA32 = smem_u32(smraw);
    const uint32_t sB32 = sA32 + MT * PITCH;

    const int tid  = threadIdx.x;
    const int lane = tid & 31, w = tid >> 5;
    const int wm = w & 3, wn = w >> 2;
    const int ibase  = (blockIdx.x >> 1) * MT;
    const int jh     = blockIdx.x & 1;
    const int jhbase = jh * 4096;
    const int iw     = ibase + wm * 32;              // warp's 32-row window
    const int pw     = (iw + B_) & (N_ - 1);         // positive-col window

    // load A stripe (once): [128 rows x 256B], padded pitch
    #pragma unroll
    for (int p = 0; p < 8; p++) {
        const int u = p * THREADS + tid;
        const int m = u >> 4, q = u & 15;
        float4 v = *(const float4*)(g_RB + (size_t)(ibase + m) * C_ + q * 8);
        *(float4*)(smraw + m * PITCH + q * 16) = v;
    }
    // load B tile 0
    #pragma unroll
    for (int p = 0; p < 8; p++) {
        const int u = p * THREADS + tid;
        const int m = u >> 4, q = u & 15;
        float4 v = *(const float4*)(g_RB + (size_t)(jhbase + m) * C_ + q * 8);
        *(float4*)(smraw + MT * PITCH + m * PITCH + q * 16) = v;
    }
    __syncthreads();

    // per-lane ldmatrix base addresses
    const int lrow = lane & 15;
    const int lkb  = (lane >> 4) * 16;
    const uint32_t aAddr = sA32 + (uint32_t)((wm * 32 + lrow) * PITCH + lkb);
    const uint32_t bOffs = (uint32_t)((wn * 64 + lrow) * PITCH + lkb);

    float rs[4] = {0.f, 0.f, 0.f, 0.f};
    const int rquad = lane >> 2;
    const int cpair = (lane & 3) * 2;

    float4 pf[8];

    for (int t = 0; t < TT; t++) {
        const uint32_t bufR = sB32 + (uint32_t)((t & 1) * (MT * PITCH));

        // register-staged prefetch of next B tile (hidden behind compute)
        if (t + 1 < TT) {
            const int gb = jhbase + (t + 1) * NT;
            #pragma unroll
            for (int p = 0; p < 8; p++) {
                const int u = p * THREADS + tid;
                const int m = u >> 4, q = u & 15;
                pf[p] = *(const float4*)(g_RB + (size_t)(gb + m) * C_ + q * 8);
            }
        }

        float acc[2][8][4];
        #pragma unroll
        for (int mf = 0; mf < 2; mf++)
            #pragma unroll
            for (int nf = 0; nf < 8; nf++)
                #pragma unroll
                for (int e = 0; e < 4; e++) acc[mf][nf][e] = 0.f;

        #pragma unroll
        for (int ks = 0; ks < 8; ks++) {
            uint32_t a[2][4];
            ldsm_x4(a[0], aAddr + (uint32_t)(ks * 32));
            ldsm_x4(a[1], aAddr + (uint32_t)(16 * PITCH + ks * 32));
            uint32_t b[4][4];
            #pragma unroll
            for (int n16 = 0; n16 < 4; n16++)
                ldsm_x4(b[n16], bufR + bOffs + (uint32_t)(n16 * 16 * PITCH + ks * 32));
            #pragma unroll
            for (int mf = 0; mf < 2; mf++)
                #pragma unroll
                for (int nf = 0; nf < 8; nf++) {
                    const int n16 = nf >> 1, g = nf & 1;
                    mma16816(acc[mf][nf], a[mf], b[n16][g], b[n16][g + 2]);
                }
        }

        // fused epilogue: exp(2*sim), mask diag, capture positive
        const int jt = jhbase + t * NT + wn * 64;
        #pragma unroll
        for (int nf = 0; nf < 8; nf++) {
            const int jb = jt + nf * 8;
            const bool hd = (unsigned)(jb - iw) < 32u;   // diag in this frag col
            const bool hp = (unsigned)(jb - pw) < 32u;   // pos  in this frag col
            if (!hd && !hp) {
                #pragma unroll
                for (int mf = 0; mf < 2; mf++)
                    #pragma unroll
                    for (int e = 0; e < 4; e++)
                        rs[mf * 2 + (e >> 1)] += ex2(acc[mf][nf][e] * LOG2E2);
            } else {
                #pragma unroll
                for (int mf = 0; mf < 2; mf++)
                    #pragma unroll
                    for (int e = 0; e < 4; e++) {
                        const int ie = iw + mf * 16 + rquad + ((e & 2) ? 8 : 0);
                        const int je = jb + cpair + (e & 1);
                        const float d = acc[mf][nf][e];
                        if (je == ((ie + B_) & (N_ - 1))) g_pos[ie] = d;
                        rs[mf * 2 + (e >> 1)] +=
                            (je == ie) ? 0.f : ex2(d * LOG2E2);
                    }
            }
        }

        // commit prefetched B tile, then barrier
        if (t + 1 < TT) {
            const uint32_t bufW = sB32 + (uint32_t)(((t + 1) & 1) * (MT * PITCH));
            #pragma unroll
            for (int p = 0; p < 8; p++) {
                const int u = p * THREADS + tid;
                const int m = u >> 4, q = u & 15;
                *(float4*)(smraw + (bufW - sA32) + m * PITCH + q * 16) = pf[p];
            }
        }
        __syncthreads();
    }

    // reduce rowsums across the lane quad (lanes sharing rows differ in bits 0-1)
    #pragma unroll
    for (int r = 0; r < 4; r++) {
        rs[r] += __shfl_xor_sync(0xffffffffu, rs[r], 1);
        rs[r] += __shfl_xor_sync(0xffffffffu, rs[r], 2);
    }
    if ((lane & 3) == 0) {
        #pragma unroll
        for (int r = 0; r < 4; r++) {
            const int row = iw + rquad + (r & 1) * 8 + (r >> 1) * 16;
            atomicAdd(&g_rowsum[row], rs[r]);
        }
    }
}

// ---------------------------------------------------------------- kernel 3
__global__ void __launch_bounds__(1024) finalize_kernel(float* __restrict__ out)
{
    const int tid = threadIdx.x;
    float s = 0.f;
    #pragma unroll
    for (int r = tid; r < N_; r += 1024) {
        const float p2 = 2.f * g_pos[r];
        s += logf(g_rowsum[r] + __expf(p2)) - p2;
    }
    #pragma unroll
    for (int o = 16; o; o >>= 1) s += __shfl_xor_sync(0xffffffffu, s, o);
    __shared__ float sw[32];
    if ((tid & 31) == 0) sw[tid >> 5] = s;
    __syncthreads();
    if (tid < 32) {
        float v = sw[tid];
        #pragma unroll
        for (int o = 16; o; o >>= 1) v += __shfl_xor_sync(0xffffffffu, v, o);
        if (tid == 0) out[0] = v * (1.0f / (float)N_);
    }
}

// ---------------------------------------------------------------- launcher
extern "C" void kernel_launch(void* const* d_in, const int* in_sizes, int n_in,
                              void* d_out, int out_size)
{
    const float* zi = (const float*)d_in[0];
    const float* zj = (const float*)d_in[1];
    float* out = (float*)d_out;

    const int smem_bytes = 3 * MT * PITCH;   // A + 2x B buffers = 104448
    cudaFuncSetAttribute(ntxent_mma_kernel,
                         cudaFuncAttributeMaxDynamicSharedMemorySize, smem_bytes);

    normalize_kernel<<<N_ / 8, 256>>>(zi, zj);
    ntxent_mma_kernel<<<128, THREADS, smem_bytes>>>();
    finalize_kernel<<<1, 1024>>>(out);
}